// round 3
// baseline (speedup 1.0000x reference)
#include <cuda_runtime.h>
#include <math.h>
#include <stdint.h>

#define NB    16
#define C     384
#define C3    1152
#define HIN   64
#define HH    16
#define L     256
#define NL    4096         // NB*L
#define HEADS 12
#define HD    32
#define EPS   1e-5f

// ---------------- scratch (device globals) ---------------------------------
// activations live as [channel][n*L + l]  (= [C][4096])
__device__ float g_xd  [C  * NL];
__device__ float g_xd2 [C  * NL];
__device__ float g_gn  [C  * NL];
__device__ float g_qkv [C3 * NL];
__device__ float g_att [NB * C * C];
__device__ float g_vals[C  * NL];
__device__ float g_stat[NB * 2];

// ---------------- depthwise 7x7 stride-4 conv + folded BatchNorm -----------
__global__ void __launch_bounds__(256) k_dwconv(
    const float* __restrict__ x, const float* __restrict__ w,
    const float* __restrict__ bg, const float* __restrict__ bb,
    const float* __restrict__ bm, const float* __restrict__ bv)
{
    __shared__ float sx[HIN * HIN];
    __shared__ float sw[49];
    int n = blockIdx.x / C, c = blockIdx.x % C;
    const float* xp = x + ((size_t)n * C + c) * (HIN * HIN);
    for (int i = threadIdx.x; i < HIN * HIN; i += 256) sx[i] = xp[i];
    if (threadIdx.x < 49) sw[threadIdx.x] = w[c * 49 + threadIdx.x];
    __syncthreads();

    float scale = bg[c] * rsqrtf(bv[c] + EPS);
    float bias  = bb[c] - bm[c] * scale;

    int oy = threadIdx.x >> 4, ox = threadIdx.x & 15;
    int iy0 = oy * 4 - 3, ix0 = ox * 4 - 3;
    float acc = 0.f;
    #pragma unroll
    for (int ky = 0; ky < 7; ky++) {
        int iy = iy0 + ky;
        if ((unsigned)iy < (unsigned)HIN) {
            #pragma unroll
            for (int kx = 0; kx < 7; kx++) {
                int ix = ix0 + kx;
                if ((unsigned)ix < (unsigned)HIN)
                    acc += sx[iy * HIN + ix] * sw[ky * 7 + kx];
            }
        }
    }
    g_xd[(size_t)c * NL + n * L + threadIdx.x] = acc * scale + bias;
}

// ---------------- GroupNorm (1 group) --------------------------------------
__device__ __forceinline__ float warpsum(float v) {
    #pragma unroll
    for (int o = 16; o; o >>= 1) v += __shfl_down_sync(0xffffffffu, v, o);
    return v;
}

__global__ void __launch_bounds__(1024) k_gnstats(const float* __restrict__ p0) {
    int n = blockIdx.x;
    float s = 0.f, s2 = 0.f;
    for (int i = threadIdx.x; i < C * L; i += 1024) {
        float t = p0[(size_t)(i >> 8) * NL + n * L + (i & 255)];
        s += t; s2 += t * t;
    }
    __shared__ float a[32], b[32];
    s = warpsum(s); s2 = warpsum(s2);
    int w = threadIdx.x >> 5, ln = threadIdx.x & 31;
    if (ln == 0) { a[w] = s; b[w] = s2; }
    __syncthreads();
    if (w == 0) {
        s = a[ln]; s2 = b[ln];
        s = warpsum(s); s2 = warpsum(s2);
        if (ln == 0) {
            float inv = 1.f / (C * L);
            float mean = s * inv;
            float var  = s2 * inv - mean * mean;
            g_stat[n * 2]     = mean;
            g_stat[n * 2 + 1] = rsqrtf(var + EPS);
        }
    }
}

__global__ void __launch_bounds__(256) k_gnapply(
    const float* __restrict__ in, float* __restrict__ out,
    const float* __restrict__ gamma, const float* __restrict__ beta)
{
    int idx = blockIdx.x * 256 + threadIdx.x;      // over C*NL
    int c = idx >> 12;
    int n = (idx & 4095) >> 8;
    float mean = g_stat[n * 2], istd = g_stat[n * 2 + 1];
    out[idx] = (in[idx] - mean) * istd * gamma[c] + beta[c];
}

// ---------------- tf32 mma + cp.async helpers ------------------------------
__device__ __forceinline__ void mma_tf32(float c[4], const uint32_t a[4], const uint32_t b[2]) {
    asm volatile(
        "mma.sync.aligned.m16n8k8.row.col.f32.tf32.tf32.f32 "
        "{%0,%1,%2,%3}, {%4,%5,%6,%7}, {%8,%9}, {%0,%1,%2,%3};"
        : "+f"(c[0]), "+f"(c[1]), "+f"(c[2]), "+f"(c[3])
        : "r"(a[0]), "r"(a[1]), "r"(a[2]), "r"(a[3]), "r"(b[0]), "r"(b[1]));
}
__device__ __forceinline__ void cpa16(uint32_t s, const float* g) {
    asm volatile("cp.async.cg.shared.global [%0], [%1], 16;" :: "r"(s), "l"(g));
}

// ---------------- tf32 tensor-core GEMM ------------------------------------
// 128x128 block tile, 8 warps (2x4), warp tile 64x32, BK=16, cp.async 2-stage.
// C = op(A,B) per batch b. TRANSB=0: B row-major [K x *] ldb ; TRANSB=1: C=A*B^T, B [N x K] ldb.
// EPI=0: C = alpha*acc ; EPI=1: C = acc + R + bias[row]
template<int TRANSB, int EPI>
__global__ void __launch_bounds__(256) k_gemm_tc(
    const float* __restrict__ A, const float* __restrict__ B, float* __restrict__ Cm,
    int K, int lda, int ldb, int ldc,
    long sA, long sB, long sC,
    float alpha, const float* __restrict__ R, long sR, const float* __restrict__ bias)
{
    __shared__ float As[2][128 * 20];
    __shared__ float Bu[2][2560];        // nontrans: [16][136] ; trans: [128][20]
    int b = blockIdx.z;
    const float* Ab = A + (size_t)b * sA;
    const float* Bb = B + (size_t)b * sB;
    int t = threadIdx.x;
    int rowBase = blockIdx.y * 128, colBase = blockIdx.x * 128;

    int ar = t >> 2, ac = (t & 3) << 2;   // A / transB loader
    int bk = t >> 5, bc = (t & 31) << 2;  // B nontrans loader

    uint32_t asB = (uint32_t)__cvta_generic_to_shared(As);
    uint32_t buB = (uint32_t)__cvta_generic_to_shared(Bu);

    auto loadStage = [&](int k0, int st) {
        const float* ap = Ab + (size_t)(rowBase + ar) * lda + k0 + ac;
        uint32_t a0 = asB + (uint32_t)(st * (128 * 20) + ar * 20 + ac) * 4;
        cpa16(a0,               ap);
        cpa16(a0 + 64 * 20 * 4, ap + (size_t)64 * lda);
        if (TRANSB) {
            const float* bp = Bb + (size_t)(colBase + ar) * ldb + k0 + ac;
            uint32_t b0 = buB + (uint32_t)(st * 2560 + ar * 20 + ac) * 4;
            cpa16(b0,               bp);
            cpa16(b0 + 64 * 20 * 4, bp + (size_t)64 * ldb);
        } else {
            const float* bp = Bb + (size_t)(k0 + bk) * ldb + colBase + bc;
            uint32_t b0 = buB + (uint32_t)(st * 2560 + bk * 136 + bc) * 4;
            cpa16(b0,                bp);
            cpa16(b0 + 8 * 136 * 4,  bp + (size_t)8 * ldb);
        }
    };

    int nIter = K >> 4;
    loadStage(0, 0);
    asm volatile("cp.async.commit_group;");

    int lane = t & 31, w = t >> 5;
    int wm = (w >> 2) * 64, wn = (w & 3) * 32;
    int lk = lane & 3, lm = lane >> 2;
    float acc[4][4][4] = {};

    for (int it = 0; it < nIter; ++it) {
        int cur = it & 1;
        if (it + 1 < nIter) {
            loadStage((it + 1) << 4, cur ^ 1);
            asm volatile("cp.async.commit_group;");
            asm volatile("cp.async.wait_group 1;");
        } else {
            asm volatile("cp.async.wait_group 0;");
        }
        __syncthreads();
        const float* Asc = As[cur];
        const float* Bsc = Bu[cur];
        #pragma unroll
        for (int kk = 0; kk < 16; kk += 8) {
            uint32_t af[4][4], bf[4][2];
            #pragma unroll
            for (int mi = 0; mi < 4; mi++) {
                int row = wm + mi * 16 + lm;
                af[mi][0] = __float_as_uint(Asc[row * 20 + kk + lk]);
                af[mi][1] = __float_as_uint(Asc[(row + 8) * 20 + kk + lk]);
                af[mi][2] = __float_as_uint(Asc[row * 20 + kk + 4 + lk]);
                af[mi][3] = __float_as_uint(Asc[(row + 8) * 20 + kk + 4 + lk]);
            }
            #pragma unroll
            for (int ni = 0; ni < 4; ni++) {
                int col = wn + ni * 8 + lm;
                if (TRANSB) {
                    bf[ni][0] = __float_as_uint(Bsc[col * 20 + kk + lk]);
                    bf[ni][1] = __float_as_uint(Bsc[col * 20 + kk + 4 + lk]);
                } else {
                    bf[ni][0] = __float_as_uint(Bsc[(kk + lk) * 136 + col]);
                    bf[ni][1] = __float_as_uint(Bsc[(kk + 4 + lk) * 136 + col]);
                }
            }
            #pragma unroll
            for (int mi = 0; mi < 4; mi++)
                #pragma unroll
                for (int ni = 0; ni < 4; ni++)
                    mma_tf32(acc[mi][ni], af[mi], bf[ni]);
        }
        __syncthreads();
    }

    float* Cb = Cm + (size_t)b * sC;
    const float* Rb = (EPI == 1) ? (R + (size_t)b * sR) : nullptr;
    #pragma unroll
    for (int mi = 0; mi < 4; mi++) {
        #pragma unroll
        for (int ni = 0; ni < 4; ni++) {
            int r0 = rowBase + wm + mi * 16 + lm;
            int cc = colBase + wn + ni * 8 + 2 * lk;
            if (EPI == 1) {
                float bv0 = bias[r0], bv1 = bias[r0 + 8];
                float2 rv0 = *(const float2*)(Rb + (size_t)r0 * ldc + cc);
                float2 rv1 = *(const float2*)(Rb + (size_t)(r0 + 8) * ldc + cc);
                *(float2*)(Cb + (size_t)r0 * ldc + cc) =
                    make_float2(acc[mi][ni][0] + rv0.x + bv0, acc[mi][ni][1] + rv0.y + bv0);
                *(float2*)(Cb + (size_t)(r0 + 8) * ldc + cc) =
                    make_float2(acc[mi][ni][2] + rv1.x + bv1, acc[mi][ni][3] + rv1.y + bv1);
            } else {
                *(float2*)(Cb + (size_t)r0 * ldc + cc) =
                    make_float2(acc[mi][ni][0] * alpha, acc[mi][ni][1] * alpha);
                *(float2*)(Cb + (size_t)(r0 + 8) * ldc + cc) =
                    make_float2(acc[mi][ni][2] * alpha, acc[mi][ni][3] * alpha);
            }
        }
    }
}

// ---------------- channel-attention softmax (rows of 384) ------------------
__global__ void __launch_bounds__(128) k_softmax(float* __restrict__ att) {
    float* p = att + (size_t)blockIdx.x * C;
    float v0 = p[threadIdx.x], v1 = p[threadIdx.x + 128], v2 = p[threadIdx.x + 256];
    float mx = fmaxf(v0, fmaxf(v1, v2));
    __shared__ float sh[4], sh2[4];
    #pragma unroll
    for (int o = 16; o; o >>= 1) mx = fmaxf(mx, __shfl_xor_sync(0xffffffffu, mx, o));
    if ((threadIdx.x & 31) == 0) sh[threadIdx.x >> 5] = mx;
    __syncthreads();
    mx = fmaxf(fmaxf(sh[0], sh[1]), fmaxf(sh[2], sh[3]));
    v0 = __expf(v0 - mx); v1 = __expf(v1 - mx); v2 = __expf(v2 - mx);
    float s = v0 + v1 + v2;
    #pragma unroll
    for (int o = 16; o; o >>= 1) s += __shfl_xor_sync(0xffffffffu, s, o);
    if ((threadIdx.x & 31) == 0) sh2[threadIdx.x >> 5] = s;
    __syncthreads();
    s = sh2[0] + sh2[1] + sh2[2] + sh2[3];
    float inv = 1.f / s;
    p[threadIdx.x] = v0 * inv; p[threadIdx.x + 128] = v1 * inv; p[threadIdx.x + 256] = v2 * inv;
}

// ---------------- spatial multi-head attention (fused, online softmax) -----
__global__ void __launch_bounds__(256) k_spattn() {
    extern __shared__ float sh[];
    float* ks = sh;
    float* vs = sh + HD * L;
    int n = blockIdx.x / HEADS, h = blockIdx.x % HEADS;
    const float* base = g_qkv + (size_t)h * (3 * HD) * NL + n * L;
    int l = threadIdx.x;
    #pragma unroll
    for (int d = 0; d < HD; d++) {
        ks[d * L + l] = base[(size_t)(HD + d) * NL + l];
        vs[d * L + l] = base[(size_t)(2 * HD + d) * NL + l];
    }
    float q[HD];
    #pragma unroll
    for (int d = 0; d < HD; d++) q[d] = base[(size_t)d * NL + l];
    __syncthreads();

    float mx = -1e30f, sum = 0.f, acc[HD];
    #pragma unroll
    for (int d = 0; d < HD; d++) acc[d] = 0.f;

    for (int m = 0; m < L; m++) {
        float s = 0.f;
        #pragma unroll
        for (int d = 0; d < HD; d++) s += q[d] * ks[d * L + m];
        s *= 0.17677669529663689f;
        float nm = fmaxf(mx, s);
        float f  = __expf(mx - nm);
        float p  = __expf(s - nm);
        sum = sum * f + p;
        #pragma unroll
        for (int d = 0; d < HD; d++) acc[d] = acc[d] * f + p * vs[d * L + m];
        mx = nm;
    }
    float inv = 1.f / sum;
    float* outp = g_vals + (size_t)h * HD * NL + n * L + l;
    #pragma unroll
    for (int d = 0; d < HD; d++) outp[(size_t)d * NL] = acc[d] * inv;
}

// ---------------- depthwise convtranspose (k=8,s=4,p=2) + residual ---------
__global__ void __launch_bounds__(256) k_up(
    const float* __restrict__ x, const float* __restrict__ w,
    const float* __restrict__ ub, float* __restrict__ out)
{
    int idx = blockIdx.x * 256 + threadIdx.x;
    int xq = idx & 63;
    int yq = (idx >> 6) & 63;
    int c  = (idx >> 12) % C;
    int n  = idx / (4096 * C);
    const float* xdp = g_xd + (size_t)c * NL + n * L;
    const float* wp  = w + c * 64;
    float acc = 0.f;
    int iy1 = (yq + 2) >> 2, ix1 = (xq + 2) >> 2;
    #pragma unroll
    for (int a = 0; a < 2; a++) {
        int iy = iy1 - a, ky = yq + 2 - 4 * iy;
        if ((unsigned)iy < 16u && (unsigned)ky < 8u) {
            #pragma unroll
            for (int b2 = 0; b2 < 2; b2++) {
                int ix = ix1 - b2, kx = xq + 2 - 4 * ix;
                if ((unsigned)ix < 16u && (unsigned)kx < 8u)
                    acc += xdp[iy * HH + ix] * wp[ky * 8 + kx];
            }
        }
    }
    out[idx] = x[idx] + acc + ub[c];
}

// ---------------- host launcher -------------------------------------------
extern "C" void kernel_launch(void* const* d_in, const int* in_sizes, int n_in,
                              void* d_out, int out_size)
{
    const float* x        = (const float*)d_in[0];
    const float* dw_w     = (const float*)d_in[1];
    const float* bn_gamma = (const float*)d_in[2];
    const float* bn_beta  = (const float*)d_in[3];
    const float* bn_mean  = (const float*)d_in[4];
    const float* bn_var   = (const float*)d_in[5];
    const float* lnch_g   = (const float*)d_in[6];
    const float* lnch_b   = (const float*)d_in[7];
    const float* pw_ch    = (const float*)d_in[8];
    const float* outch_w  = (const float*)d_in[9];
    const float* outch_b  = (const float*)d_in[10];
    const float* lnsp_g   = (const float*)d_in[11];
    const float* lnsp_b   = (const float*)d_in[12];
    const float* pw_sp    = (const float*)d_in[13];
    const float* outsp_w  = (const float*)d_in[14];
    const float* outsp_b  = (const float*)d_in[15];
    const float* up_w     = (const float*)d_in[16];
    const float* up_b     = (const float*)d_in[17];
    float* out = (float*)d_out;

    float *xd, *xd2, *gn, *qkv, *att, *vals;
    cudaGetSymbolAddress((void**)&xd,   g_xd);
    cudaGetSymbolAddress((void**)&xd2,  g_xd2);
    cudaGetSymbolAddress((void**)&gn,   g_gn);
    cudaGetSymbolAddress((void**)&qkv,  g_qkv);
    cudaGetSymbolAddress((void**)&att,  g_att);
    cudaGetSymbolAddress((void**)&vals, g_vals);

    // 1) downsample conv + BN  -> xd [C][NL]
    k_dwconv<<<NB * C, 256>>>(x, dw_w, bn_gamma, bn_beta, bn_mean, bn_var);

    // 2-3) GroupNorm #1
    k_gnstats<<<NB, 1024>>>(xd);
    k_gnapply<<<(C * NL) / 256, 256>>>(xd, gn, lnch_g, lnch_b);

    // 4) qkv = pw_ch [1152,384] @ gn [384,4096]  (one big GEMM)
    k_gemm_tc<0, 0><<<dim3(NL / 128, C3 / 128, 1), 256>>>(
        pw_ch, gn, qkv, C, C, NL, NL, 0, 0, 0, 1.f, nullptr, 0, nullptr);

    // 5) scores[n] = q[n] @ k[n]^T / 16   (batched, strided views, K=256)
    k_gemm_tc<1, 0><<<dim3(C / 128, C / 128, NB), 256>>>(
        qkv, qkv + (size_t)C * NL, att, L, NL, NL, C,
        L, L, (long)C * C, 1.f / 16.f, nullptr, 0, nullptr);

    // 6) softmax rows
    k_softmax<<<NB * C, 128>>>(att);

    // 7) vals[n] = att[n] @ v[n]   (batched)
    k_gemm_tc<0, 0><<<dim3(L / 128, C / 128, NB), 256>>>(
        att, qkv + (size_t)2 * C * NL, vals, C, C, NL, NL,
        (long)C * C, L, L, 1.f, nullptr, 0, nullptr);

    // 8) xd2 = outch_w @ vals + xd + outch_b   (one big GEMM)
    k_gemm_tc<0, 1><<<dim3(NL / 128, C / 128, 1), 256>>>(
        outch_w, vals, xd2, C, C, NL, NL, 0, 0, 0,
        1.f, xd, 0, outch_b);

    // 9-10) GroupNorm #2
    k_gnstats<<<NB, 1024>>>(xd2);
    k_gnapply<<<(C * NL) / 256, 256>>>(xd2, gn, lnsp_g, lnsp_b);

    // 11) qkv = pw_sp @ gn   (one big GEMM)
    k_gemm_tc<0, 0><<<dim3(NL / 128, C3 / 128, 1), 256>>>(
        pw_sp, gn, qkv, C, C, NL, NL, 0, 0, 0, 1.f, nullptr, 0, nullptr);

    // 12) fused spatial attention
    cudaFuncSetAttribute(k_spattn, cudaFuncAttributeMaxDynamicSharedMemorySize,
                         2 * HD * L * sizeof(float));
    k_spattn<<<NB * HEADS, 256, 2 * HD * L * sizeof(float)>>>();

    // 13) xd = outsp_w @ vals + xd2 + outsp_b   (one big GEMM)
    k_gemm_tc<0, 1><<<dim3(NL / 128, C / 128, 1), 256>>>(
        outsp_w, vals, xd, C, C, NL, NL, 0, 0, 0,
        1.f, xd2, 0, outsp_b);

    // 14) upsample transposed conv + residual
    k_up<<<(NB * C * HIN * HIN) / 256, 256>>>(x, up_w, up_b, out);
}

// round 5
// speedup vs baseline: 1.5964x; 1.5964x over previous
#include <cuda_runtime.h>
#include <math.h>
#include <stdint.h>

#define NB    16
#define C     384
#define C3    1152
#define HIN   64
#define HH    16
#define L     256
#define HEADS 12
#define HD    32
#define EPS   1e-5f

// ---------------- scratch (device globals) ---------------------------------
// activations: per-sample compact [N][C][L]
__device__ float g_xd  [NB * C  * L];
__device__ float g_xd2 [NB * C  * L];
__device__ float g_gn  [NB * C  * L];
__device__ float g_qkv [NB * C3 * L];
__device__ float g_att [NB * C  * C];
__device__ float g_vals[NB * C  * L];
__device__ float g_stat[NB * 2];

// ---------------- depthwise 7x7 stride-4 conv + folded BatchNorm -----------
__global__ void __launch_bounds__(256) k_dwconv(
    const float* __restrict__ x, const float* __restrict__ w,
    const float* __restrict__ bg, const float* __restrict__ bb,
    const float* __restrict__ bm, const float* __restrict__ bv)
{
    __shared__ float sx[HIN * HIN];
    __shared__ float sw[49];
    int n = blockIdx.x / C, c = blockIdx.x % C;
    const float* xp = x + ((size_t)n * C + c) * (HIN * HIN);
    for (int i = threadIdx.x; i < HIN * HIN; i += 256) sx[i] = xp[i];
    if (threadIdx.x < 49) sw[threadIdx.x] = w[c * 49 + threadIdx.x];
    __syncthreads();

    float scale = bg[c] * rsqrtf(bv[c] + EPS);
    float bias  = bb[c] - bm[c] * scale;

    int oy = threadIdx.x >> 4, ox = threadIdx.x & 15;
    int iy0 = oy * 4 - 3, ix0 = ox * 4 - 3;
    float acc = 0.f;
    #pragma unroll
    for (int ky = 0; ky < 7; ky++) {
        int iy = iy0 + ky;
        if ((unsigned)iy < (unsigned)HIN) {
            #pragma unroll
            for (int kx = 0; kx < 7; kx++) {
                int ix = ix0 + kx;
                if ((unsigned)ix < (unsigned)HIN)
                    acc += sx[iy * HIN + ix] * sw[ky * 7 + kx];
            }
        }
    }
    g_xd[((size_t)n * C + c) * L + threadIdx.x] = acc * scale + bias;
}

// ---------------- GroupNorm (1 group) --------------------------------------
__device__ __forceinline__ float warpsum(float v) {
    #pragma unroll
    for (int o = 16; o; o >>= 1) v += __shfl_down_sync(0xffffffffu, v, o);
    return v;
}

__global__ void __launch_bounds__(1024) k_gnstats(const float* __restrict__ p0) {
    const float* p = p0 + (size_t)blockIdx.x * C * L;
    float s = 0.f, s2 = 0.f;
    for (int i = threadIdx.x; i < C * L; i += 1024) {
        float t = p[i]; s += t; s2 += t * t;
    }
    __shared__ float a[32], b[32];
    s = warpsum(s); s2 = warpsum(s2);
    int w = threadIdx.x >> 5, ln = threadIdx.x & 31;
    if (ln == 0) { a[w] = s; b[w] = s2; }
    __syncthreads();
    if (w == 0) {
        s = a[ln]; s2 = b[ln];
        s = warpsum(s); s2 = warpsum(s2);
        if (ln == 0) {
            float inv = 1.f / (C * L);
            float mean = s * inv;
            float var  = s2 * inv - mean * mean;
            g_stat[blockIdx.x * 2]     = mean;
            g_stat[blockIdx.x * 2 + 1] = rsqrtf(var + EPS);
        }
    }
}

__global__ void __launch_bounds__(256) k_gnapply(
    const float* __restrict__ in, float* __restrict__ out,
    const float* __restrict__ gamma, const float* __restrict__ beta)
{
    int idx = blockIdx.x * 256 + threadIdx.x;
    int n = idx / (C * L);
    int c = (idx / L) % C;
    float mean = g_stat[n * 2], istd = g_stat[n * 2 + 1];
    out[idx] = (in[idx] - mean) * istd * gamma[c] + beta[c];
}

// ---------------- tf32 mma + cp.async helpers ------------------------------
__device__ __forceinline__ void mma_tf32(float c[4], const uint32_t a[4], const uint32_t b[2]) {
    asm volatile(
        "mma.sync.aligned.m16n8k8.row.col.f32.tf32.tf32.f32 "
        "{%0,%1,%2,%3}, {%4,%5,%6,%7}, {%8,%9}, {%0,%1,%2,%3};"
        : "+f"(c[0]), "+f"(c[1]), "+f"(c[2]), "+f"(c[3])
        : "r"(a[0]), "r"(a[1]), "r"(a[2]), "r"(a[3]), "r"(b[0]), "r"(b[1]));
}
__device__ __forceinline__ void cpa16(uint32_t s, const float* g) {
    asm volatile("cp.async.cg.shared.global [%0], [%1], 16;" :: "r"(s), "l"(g));
}

// ---------------- tf32 tensor-core GEMM ------------------------------------
// 128x128 block tile, 8 warps (2x4), warp tile 64x32, BK=16, cp.async 2-stage.
// Per batch b: TRANSB=0: C=A*B, B row-major [K x N] ldb ; TRANSB=1: C=A*B^T, B [N x K] ldb.
// EPI=0: C = alpha*acc ; EPI=1: C = acc + R + bias[row]
template<int TRANSB, int EPI>
__global__ void __launch_bounds__(256) k_gemm_tc(
    const float* __restrict__ A, const float* __restrict__ B, float* __restrict__ Cm,
    int K, int lda, int ldb, int ldc,
    long sA, long sB, long sC,
    float alpha, const float* __restrict__ R, long sR, const float* __restrict__ bias)
{
    __shared__ float As[2][128 * 20];
    __shared__ float Bu[2][2560];        // nontrans: [16][136] ; trans: [128][20]
    int b = blockIdx.z;
    const float* Ab = A + (size_t)b * sA;
    const float* Bb = B + (size_t)b * sB;
    int t = threadIdx.x;
    int rowBase = blockIdx.y * 128, colBase = blockIdx.x * 128;

    int ar = t >> 2, ac = (t & 3) << 2;   // A / transB loader
    int bk = t >> 5, bc = (t & 31) << 2;  // B nontrans loader

    uint32_t asB = (uint32_t)__cvta_generic_to_shared(As);
    uint32_t buB = (uint32_t)__cvta_generic_to_shared(Bu);

    auto loadStage = [&](int k0, int st) {
        const float* ap = Ab + (size_t)(rowBase + ar) * lda + k0 + ac;
        uint32_t a0 = asB + (uint32_t)(st * (128 * 20) + ar * 20 + ac) * 4;
        cpa16(a0,               ap);
        cpa16(a0 + 64 * 20 * 4, ap + (size_t)64 * lda);
        if (TRANSB) {
            const float* bp = Bb + (size_t)(colBase + ar) * ldb + k0 + ac;
            uint32_t b0 = buB + (uint32_t)(st * 2560 + ar * 20 + ac) * 4;
            cpa16(b0,               bp);
            cpa16(b0 + 64 * 20 * 4, bp + (size_t)64 * ldb);
        } else {
            const float* bp = Bb + (size_t)(k0 + bk) * ldb + colBase + bc;
            uint32_t b0 = buB + (uint32_t)(st * 2560 + bk * 136 + bc) * 4;
            cpa16(b0,                bp);
            cpa16(b0 + 8 * 136 * 4,  bp + (size_t)8 * ldb);
        }
    };

    int nIter = K >> 4;
    loadStage(0, 0);
    asm volatile("cp.async.commit_group;");

    int lane = t & 31, w = t >> 5;
    int wm = (w >> 2) * 64, wn = (w & 3) * 32;
    int lk = lane & 3, lm = lane >> 2;
    float acc[4][4][4] = {};

    for (int it = 0; it < nIter; ++it) {
        int cur = it & 1;
        if (it + 1 < nIter) {
            loadStage((it + 1) << 4, cur ^ 1);
            asm volatile("cp.async.commit_group;");
            asm volatile("cp.async.wait_group 1;");
        } else {
            asm volatile("cp.async.wait_group 0;");
        }
        __syncthreads();
        const float* Asc = As[cur];
        const float* Bsc = Bu[cur];
        #pragma unroll
        for (int kk = 0; kk < 16; kk += 8) {
            uint32_t af[4][4], bf[4][2];
            #pragma unroll
            for (int mi = 0; mi < 4; mi++) {
                int row = wm + mi * 16 + lm;
                af[mi][0] = __float_as_uint(Asc[row * 20 + kk + lk]);
                af[mi][1] = __float_as_uint(Asc[(row + 8) * 20 + kk + lk]);
                af[mi][2] = __float_as_uint(Asc[row * 20 + kk + 4 + lk]);
                af[mi][3] = __float_as_uint(Asc[(row + 8) * 20 + kk + 4 + lk]);
            }
            #pragma unroll
            for (int ni = 0; ni < 4; ni++) {
                int col = wn + ni * 8 + lm;
                if (TRANSB) {
                    bf[ni][0] = __float_as_uint(Bsc[col * 20 + kk + lk]);
                    bf[ni][1] = __float_as_uint(Bsc[col * 20 + kk + 4 + lk]);
                } else {
                    bf[ni][0] = __float_as_uint(Bsc[(kk + lk) * 136 + col]);
                    bf[ni][1] = __float_as_uint(Bsc[(kk + 4 + lk) * 136 + col]);
                }
            }
            #pragma unroll
            for (int mi = 0; mi < 4; mi++)
                #pragma unroll
                for (int ni = 0; ni < 4; ni++)
                    mma_tf32(acc[mi][ni], af[mi], bf[ni]);
        }
        __syncthreads();
    }

    float* Cb = Cm + (size_t)b * sC;
    const float* Rb = (EPI == 1) ? (R + (size_t)b * sR) : nullptr;
    #pragma unroll
    for (int mi = 0; mi < 4; mi++) {
        #pragma unroll
        for (int ni = 0; ni < 4; ni++) {
            int r0 = rowBase + wm + mi * 16 + lm;
            int cc = colBase + wn + ni * 8 + 2 * lk;
            if (EPI == 1) {
                float bv0 = bias[r0], bv1 = bias[r0 + 8];
                float2 rv0 = *(const float2*)(Rb + (size_t)r0 * ldc + cc);
                float2 rv1 = *(const float2*)(Rb + (size_t)(r0 + 8) * ldc + cc);
                *(float2*)(Cb + (size_t)r0 * ldc + cc) =
                    make_float2(acc[mi][ni][0] + rv0.x + bv0, acc[mi][ni][1] + rv0.y + bv0);
                *(float2*)(Cb + (size_t)(r0 + 8) * ldc + cc) =
                    make_float2(acc[mi][ni][2] + rv1.x + bv1, acc[mi][ni][3] + rv1.y + bv1);
            } else {
                *(float2*)(Cb + (size_t)r0 * ldc + cc) =
                    make_float2(acc[mi][ni][0] * alpha, acc[mi][ni][1] * alpha);
                *(float2*)(Cb + (size_t)(r0 + 8) * ldc + cc) =
                    make_float2(acc[mi][ni][2] * alpha, acc[mi][ni][3] * alpha);
            }
        }
    }
}

// ---------------- channel-attention softmax (rows of 384) ------------------
__global__ void __launch_bounds__(128) k_softmax(float* __restrict__ att) {
    float* p = att + (size_t)blockIdx.x * C;
    float v0 = p[threadIdx.x], v1 = p[threadIdx.x + 128], v2 = p[threadIdx.x + 256];
    float mx = fmaxf(v0, fmaxf(v1, v2));
    __shared__ float sh[4], sh2[4];
    #pragma unroll
    for (int o = 16; o; o >>= 1) mx = fmaxf(mx, __shfl_xor_sync(0xffffffffu, mx, o));
    if ((threadIdx.x & 31) == 0) sh[threadIdx.x >> 5] = mx;
    __syncthreads();
    mx = fmaxf(fmaxf(sh[0], sh[1]), fmaxf(sh[2], sh[3]));
    v0 = __expf(v0 - mx); v1 = __expf(v1 - mx); v2 = __expf(v2 - mx);
    float s = v0 + v1 + v2;
    #pragma unroll
    for (int o = 16; o; o >>= 1) s += __shfl_xor_sync(0xffffffffu, s, o);
    if ((threadIdx.x & 31) == 0) sh2[threadIdx.x >> 5] = s;
    __syncthreads();
    s = sh2[0] + sh2[1] + sh2[2] + sh2[3];
    float inv = 1.f / s;
    p[threadIdx.x] = v0 * inv; p[threadIdx.x + 128] = v1 * inv; p[threadIdx.x + 256] = v2 * inv;
}

// ---------------- spatial multi-head attention (fused, online softmax) -----
__global__ void __launch_bounds__(256) k_spattn() {
    extern __shared__ float sh[];
    float* ks = sh;
    float* vs = sh + HD * L;
    int n = blockIdx.x / HEADS, h = blockIdx.x % HEADS;
    const float* base = g_qkv + (size_t)n * C3 * L + (size_t)h * (3 * HD) * L;
    int l = threadIdx.x;
    #pragma unroll
    for (int d = 0; d < HD; d++) {
        ks[d * L + l] = base[(HD + d) * L + l];
        vs[d * L + l] = base[(2 * HD + d) * L + l];
    }
    float q[HD];
    #pragma unroll
    for (int d = 0; d < HD; d++) q[d] = base[d * L + l];
    __syncthreads();

    float mx = -1e30f, sum = 0.f, acc[HD];
    #pragma unroll
    for (int d = 0; d < HD; d++) acc[d] = 0.f;

    for (int m = 0; m < L; m++) {
        float s = 0.f;
        #pragma unroll
        for (int d = 0; d < HD; d++) s += q[d] * ks[d * L + m];
        s *= 0.17677669529663689f;
        float nm = fmaxf(mx, s);
        float f  = __expf(mx - nm);
        float p  = __expf(s - nm);
        sum = sum * f + p;
        #pragma unroll
        for (int d = 0; d < HD; d++) acc[d] = acc[d] * f + p * vs[d * L + m];
        mx = nm;
    }
    float inv = 1.f / sum;
    float* outp = g_vals + (size_t)n * C * L + (size_t)h * HD * L + l;
    #pragma unroll
    for (int d = 0; d < HD; d++) outp[d * L] = acc[d] * inv;
}

// ---------------- depthwise convtranspose (k=8,s=4,p=2) + residual ---------
__global__ void __launch_bounds__(256) k_up(
    const float* __restrict__ x, const float* __restrict__ w,
    const float* __restrict__ ub, float* __restrict__ out)
{
    int idx = blockIdx.x * 256 + threadIdx.x;
    int xq = idx & 63;
    int yq = (idx >> 6) & 63;
    int c  = (idx >> 12) % C;
    int n  = idx / (4096 * C);
    const float* xdp = g_xd + ((size_t)n * C + c) * L;
    const float* wp  = w + c * 64;
    float acc = 0.f;
    int iy1 = (yq + 2) >> 2, ix1 = (xq + 2) >> 2;
    #pragma unroll
    for (int a = 0; a < 2; a++) {
        int iy = iy1 - a, ky = yq + 2 - 4 * iy;
        if ((unsigned)iy < 16u && (unsigned)ky < 8u) {
            #pragma unroll
            for (int b2 = 0; b2 < 2; b2++) {
                int ix = ix1 - b2, kx = xq + 2 - 4 * ix;
                if ((unsigned)ix < 16u && (unsigned)kx < 8u)
                    acc += xdp[iy * HH + ix] * wp[ky * 8 + kx];
            }
        }
    }
    out[idx] = x[idx] + acc + ub[c];
}

// ---------------- host launcher -------------------------------------------
extern "C" void kernel_launch(void* const* d_in, const int* in_sizes, int n_in,
                              void* d_out, int out_size)
{
    const float* x        = (const float*)d_in[0];
    const float* dw_w     = (const float*)d_in[1];
    const float* bn_gamma = (const float*)d_in[2];
    const float* bn_beta  = (const float*)d_in[3];
    const float* bn_mean  = (const float*)d_in[4];
    const float* bn_var   = (const float*)d_in[5];
    const float* lnch_g   = (const float*)d_in[6];
    const float* lnch_b   = (const float*)d_in[7];
    const float* pw_ch    = (const float*)d_in[8];
    const float* outch_w  = (const float*)d_in[9];
    const float* outch_b  = (const float*)d_in[10];
    const float* lnsp_g   = (const float*)d_in[11];
    const float* lnsp_b   = (const float*)d_in[12];
    const float* pw_sp    = (const float*)d_in[13];
    const float* outsp_w  = (const float*)d_in[14];
    const float* outsp_b  = (const float*)d_in[15];
    const float* up_w     = (const float*)d_in[16];
    const float* up_b     = (const float*)d_in[17];
    float* out = (float*)d_out;

    float *xd, *xd2, *gn, *qkv, *att, *vals;
    cudaGetSymbolAddress((void**)&xd,   g_xd);
    cudaGetSymbolAddress((void**)&xd2,  g_xd2);
    cudaGetSymbolAddress((void**)&gn,   g_gn);
    cudaGetSymbolAddress((void**)&qkv,  g_qkv);
    cudaGetSymbolAddress((void**)&att,  g_att);
    cudaGetSymbolAddress((void**)&vals, g_vals);

    // 1) downsample conv + BN
    k_dwconv<<<NB * C, 256>>>(x, dw_w, bn_gamma, bn_beta, bn_mean, bn_var);

    // 2-3) GroupNorm #1
    k_gnstats<<<NB, 1024>>>(xd);
    k_gnapply<<<(NB * C * L) / 256, 256>>>(xd, gn, lnch_g, lnch_b);

    // 4) qkv[n] = pw_ch [1152,384] @ gn[n] [384,256]   (batched; 288 blocks)
    k_gemm_tc<0, 0><<<dim3(L / 128, C3 / 128, NB), 256>>>(
        pw_ch, gn, qkv, C, C, L, L,
        0, (long)C * L, (long)C3 * L, 1.f, nullptr, 0, nullptr);

    // 5) scores[n] = q[n] @ k[n]^T / 16   [384x384], K=256
    k_gemm_tc<1, 0><<<dim3(C / 128, C / 128, NB), 256>>>(
        qkv, qkv + (size_t)C * L, att, L, L, L, C,
        (long)C3 * L, (long)C3 * L, (long)C * C,
        1.f / 16.f, nullptr, 0, nullptr);

    // 6) softmax rows
    k_softmax<<<NB * C, 128>>>(att);

    // 7) vals[n] = att[n] @ v[n]   [384x256], K=384
    k_gemm_tc<0, 0><<<dim3(L / 128, C / 128, NB), 256>>>(
        att, qkv + (size_t)2 * C * L, vals, C, C, L, L,
        (long)C * C, (long)C3 * L, (long)C * L,
        1.f, nullptr, 0, nullptr);

    // 8) xd2[n] = outch_w @ vals[n] + xd[n] + outch_b
    k_gemm_tc<0, 1><<<dim3(L / 128, C / 128, NB), 256>>>(
        outch_w, vals, xd2, C, C, L, L,
        0, (long)C * L, (long)C * L,
        1.f, xd, (long)C * L, outch_b);

    // 9-10) GroupNorm #2
    k_gnstats<<<NB, 1024>>>(xd2);
    k_gnapply<<<(NB * C * L) / 256, 256>>>(xd2, gn, lnsp_g, lnsp_b);

    // 11) qkv[n] = pw_sp @ gn[n]
    k_gemm_tc<0, 0><<<dim3(L / 128, C3 / 128, NB), 256>>>(
        pw_sp, gn, qkv, C, C, L, L,
        0, (long)C * L, (long)C3 * L, 1.f, nullptr, 0, nullptr);

    // 12) fused spatial attention
    cudaFuncSetAttribute(k_spattn, cudaFuncAttributeMaxDynamicSharedMemorySize,
                         2 * HD * L * sizeof(float));
    k_spattn<<<NB * HEADS, 256, 2 * HD * L * sizeof(float)>>>();

    // 13) xd[n] = outsp_w @ vals[n] + xd2[n] + outsp_b
    k_gemm_tc<0, 1><<<dim3(L / 128, C / 128, NB), 256>>>(
        outsp_w, vals, xd, C, C, L, L,
        0, (long)C * L, (long)C * L,
        1.f, xd2, (long)C * L, outsp_b);

    // 14) upsample transposed conv + residual
    k_up<<<(NB * C * HIN * HIN) / 256, 256>>>(x, up_w, up_b, out);
}

// round 6
// speedup vs baseline: 2.4221x; 1.5172x over previous
#include <cuda_runtime.h>
#include <math.h>
#include <stdint.h>

#define NB    16
#define C     384
#define C3    1152
#define HIN   64
#define HH    16
#define L     256
#define HEADS 12
#define HD    32
#define EPS   1e-5f
#define SPAD  36

// ---------------- scratch (device globals) ---------------------------------
__device__ float g_xd  [NB * C  * L];
__device__ float g_xd2 [NB * C  * L];
__device__ float g_gn  [NB * C  * L];
__device__ float g_qkv [NB * C3 * L];
__device__ float g_att [NB * C  * C];
__device__ float g_vals[NB * C  * L];
__device__ float g_stat[NB * 2];

// ---------------- depthwise 7x7 stride-4 conv + folded BatchNorm -----------
__global__ void __launch_bounds__(256) k_dwconv(
    const float* __restrict__ x, const float* __restrict__ w,
    const float* __restrict__ bg, const float* __restrict__ bb,
    const float* __restrict__ bm, const float* __restrict__ bv)
{
    __shared__ float sx[HIN * HIN];
    __shared__ float sw[49];
    int n = blockIdx.x / C, c = blockIdx.x % C;
    const float4* xp4 = (const float4*)(x + ((size_t)n * C + c) * (HIN * HIN));
    #pragma unroll
    for (int i = 0; i < 4; i++)
        ((float4*)sx)[threadIdx.x + i * 256] = xp4[threadIdx.x + i * 256];
    if (threadIdx.x < 49) sw[threadIdx.x] = w[c * 49 + threadIdx.x];
    __syncthreads();

    float scale = bg[c] * rsqrtf(bv[c] + EPS);
    float bias  = bb[c] - bm[c] * scale;

    int oy = threadIdx.x >> 4, ox = threadIdx.x & 15;
    int iy0 = oy * 4 - 3, ix0 = ox * 4 - 3;
    float acc = 0.f;
    #pragma unroll
    for (int ky = 0; ky < 7; ky++) {
        int iy = iy0 + ky;
        if ((unsigned)iy < (unsigned)HIN) {
            #pragma unroll
            for (int kx = 0; kx < 7; kx++) {
                int ix = ix0 + kx;
                if ((unsigned)ix < (unsigned)HIN)
                    acc += sx[iy * HIN + ix] * sw[ky * 7 + kx];
            }
        }
    }
    g_xd[((size_t)n * C + c) * L + threadIdx.x] = acc * scale + bias;
}

// ---------------- GroupNorm (1 group) --------------------------------------
__device__ __forceinline__ float warpsum(float v) {
    #pragma unroll
    for (int o = 16; o; o >>= 1) v += __shfl_down_sync(0xffffffffu, v, o);
    return v;
}

__global__ void __launch_bounds__(1024) k_gnstats(const float* __restrict__ p0) {
    const float4* p = (const float4*)(p0 + (size_t)blockIdx.x * C * L);
    float s = 0.f, s2 = 0.f;
    for (int i = threadIdx.x; i < C * L / 4; i += 1024) {
        float4 t = p[i];
        s  += t.x + t.y + t.z + t.w;
        s2 += t.x * t.x + t.y * t.y + t.z * t.z + t.w * t.w;
    }
    __shared__ float a[32], b[32];
    s = warpsum(s); s2 = warpsum(s2);
    int w = threadIdx.x >> 5, ln = threadIdx.x & 31;
    if (ln == 0) { a[w] = s; b[w] = s2; }
    __syncthreads();
    if (w == 0) {
        s = a[ln]; s2 = b[ln];
        s = warpsum(s); s2 = warpsum(s2);
        if (ln == 0) {
            float inv = 1.f / (C * L);
            float mean = s * inv;
            float var  = s2 * inv - mean * mean;
            g_stat[blockIdx.x * 2]     = mean;
            g_stat[blockIdx.x * 2 + 1] = rsqrtf(var + EPS);
        }
    }
}

__global__ void __launch_bounds__(256) k_gnapply(
    const float* __restrict__ in, float* __restrict__ out,
    const float* __restrict__ gamma, const float* __restrict__ beta)
{
    int i4 = blockIdx.x * 256 + threadIdx.x;       // over C*NL/4 elements
    int idx = i4 << 2;
    int n = idx / (C * L);
    int c = (idx / L) % C;
    float mean = g_stat[n * 2], istd = g_stat[n * 2 + 1];
    float g = gamma[c] * istd, bt = beta[c] - mean * g;
    float4 v = ((const float4*)in)[i4];
    ((float4*)out)[i4] = make_float4(v.x * g + bt, v.y * g + bt,
                                     v.z * g + bt, v.w * g + bt);
}

// ---------------- tf32 mma + cp.async helpers ------------------------------
__device__ __forceinline__ void mma_tf32(float c[4], const uint32_t a[4], const uint32_t b[2]) {
    asm volatile(
        "mma.sync.aligned.m16n8k8.row.col.f32.tf32.tf32.f32 "
        "{%0,%1,%2,%3}, {%4,%5,%6,%7}, {%8,%9}, {%0,%1,%2,%3};"
        : "+f"(c[0]), "+f"(c[1]), "+f"(c[2]), "+f"(c[3])
        : "r"(a[0]), "r"(a[1]), "r"(a[2]), "r"(a[3]), "r"(b[0]), "r"(b[1]));
}
__device__ __forceinline__ void cpa16(uint32_t s, const float* g) {
    asm volatile("cp.async.cg.shared.global [%0], [%1], 16;" :: "r"(s), "l"(g));
}

// ---------------- tf32 tensor-core GEMM, 3-stage pipeline ------------------
// 128x128 block tile, 8 warps (2x4), warp tile 64x32, BK=16, cp.async 3-stage.
// TRANSB=0: C=A*B, B [K x N] ldb ; TRANSB=1: C=A*B^T, B [N x K] ldb.
// EPI=0: C = alpha*acc ; EPI=1: C = acc + R + bias[row]
#define STG 2560   // floats per stage (A: 128*20=2560; B: max(16*136, 128*20)=2560)
template<int TRANSB, int EPI>
__global__ void __launch_bounds__(256) k_gemm_tc(
    const float* __restrict__ A, const float* __restrict__ B, float* __restrict__ Cm,
    int K, int lda, int ldb, int ldc,
    long sA, long sB, long sC,
    float alpha, const float* __restrict__ R, long sR, const float* __restrict__ bias)
{
    extern __shared__ float smem[];          // [3*STG] A | [3*STG] B = 60KB
    int b = blockIdx.z;
    const float* Ab = A + (size_t)b * sA;
    const float* Bb = B + (size_t)b * sB;
    int t = threadIdx.x;
    int rowBase = blockIdx.y * 128, colBase = blockIdx.x * 128;

    int ar = t >> 2, ac = (t & 3) << 2;
    int bk = t >> 5, bc = (t & 31) << 2;

    uint32_t asB = (uint32_t)__cvta_generic_to_shared(smem);
    uint32_t buB = (uint32_t)__cvta_generic_to_shared(smem + 3 * STG);

    auto loadStage = [&](int k0, int st) {
        const float* ap = Ab + (size_t)(rowBase + ar) * lda + k0 + ac;
        uint32_t a0 = asB + (uint32_t)(st * STG + ar * 20 + ac) * 4;
        cpa16(a0,               ap);
        cpa16(a0 + 64 * 20 * 4, ap + (size_t)64 * lda);
        if (TRANSB) {
            const float* bp = Bb + (size_t)(colBase + ar) * ldb + k0 + ac;
            uint32_t b0 = buB + (uint32_t)(st * STG + ar * 20 + ac) * 4;
            cpa16(b0,               bp);
            cpa16(b0 + 64 * 20 * 4, bp + (size_t)64 * ldb);
        } else {
            const float* bp = Bb + (size_t)(k0 + bk) * ldb + colBase + bc;
            uint32_t b0 = buB + (uint32_t)(st * STG + bk * 136 + bc) * 4;
            cpa16(b0,                bp);
            cpa16(b0 + 8 * 136 * 4,  bp + (size_t)8 * ldb);
        }
    };

    int nIter = K >> 4;                      // >= 2 for all our shapes
    loadStage(0, 0);
    asm volatile("cp.async.commit_group;");
    loadStage(16, 1);
    asm volatile("cp.async.commit_group;");

    int lane = t & 31, w = t >> 5;
    int wm = (w >> 2) * 64, wn = (w & 3) * 32;
    int lk = lane & 3, lm = lane >> 2;
    float acc[4][4][4] = {};

    int cur = 0;
    for (int it = 0; it < nIter; ++it) {
        if (it + 2 < nIter) { asm volatile("cp.async.wait_group 1;"); }
        else               { asm volatile("cp.async.wait_group 0;"); }
        __syncthreads();
        if (it + 2 < nIter) {
            int st = cur - 1; if (st < 0) st += 3;   // (cur+2)%3
            loadStage((it + 2) << 4, st);
            asm volatile("cp.async.commit_group;");
        }
        const float* Asc = smem + cur * STG;
        const float* Bsc = smem + 3 * STG + cur * STG;
        #pragma unroll
        for (int kk = 0; kk < 16; kk += 8) {
            uint32_t af[4][4], bf[4][2];
            #pragma unroll
            for (int mi = 0; mi < 4; mi++) {
                int row = wm + mi * 16 + lm;
                af[mi][0] = __float_as_uint(Asc[row * 20 + kk + lk]);
                af[mi][1] = __float_as_uint(Asc[(row + 8) * 20 + kk + lk]);
                af[mi][2] = __float_as_uint(Asc[row * 20 + kk + 4 + lk]);
                af[mi][3] = __float_as_uint(Asc[(row + 8) * 20 + kk + 4 + lk]);
            }
            #pragma unroll
            for (int ni = 0; ni < 4; ni++) {
                int col = wn + ni * 8 + lm;
                if (TRANSB) {
                    bf[ni][0] = __float_as_uint(Bsc[col * 20 + kk + lk]);
                    bf[ni][1] = __float_as_uint(Bsc[col * 20 + kk + 4 + lk]);
                } else {
                    bf[ni][0] = __float_as_uint(Bsc[(kk + lk) * 136 + col]);
                    bf[ni][1] = __float_as_uint(Bsc[(kk + 4 + lk) * 136 + col]);
                }
            }
            #pragma unroll
            for (int mi = 0; mi < 4; mi++)
                #pragma unroll
                for (int ni = 0; ni < 4; ni++)
                    mma_tf32(acc[mi][ni], af[mi], bf[ni]);
        }
        cur++; if (cur == 3) cur = 0;
    }

    float* Cb = Cm + (size_t)b * sC;
    const float* Rb = (EPI == 1) ? (R + (size_t)b * sR) : nullptr;
    #pragma unroll
    for (int mi = 0; mi < 4; mi++) {
        #pragma unroll
        for (int ni = 0; ni < 4; ni++) {
            int r0 = rowBase + wm + mi * 16 + lm;
            int cc = colBase + wn + ni * 8 + 2 * lk;
            if (EPI == 1) {
                float bv0 = bias[r0], bv1 = bias[r0 + 8];
                float2 rv0 = *(const float2*)(Rb + (size_t)r0 * ldc + cc);
                float2 rv1 = *(const float2*)(Rb + (size_t)(r0 + 8) * ldc + cc);
                *(float2*)(Cb + (size_t)r0 * ldc + cc) =
                    make_float2(acc[mi][ni][0] + rv0.x + bv0, acc[mi][ni][1] + rv0.y + bv0);
                *(float2*)(Cb + (size_t)(r0 + 8) * ldc + cc) =
                    make_float2(acc[mi][ni][2] + rv1.x + bv1, acc[mi][ni][3] + rv1.y + bv1);
            } else {
                *(float2*)(Cb + (size_t)r0 * ldc + cc) =
                    make_float2(acc[mi][ni][0] * alpha, acc[mi][ni][1] * alpha);
                *(float2*)(Cb + (size_t)(r0 + 8) * ldc + cc) =
                    make_float2(acc[mi][ni][2] * alpha, acc[mi][ni][3] * alpha);
            }
        }
    }
}

// ---------------- channel-attention softmax (rows of 384) ------------------
__global__ void __launch_bounds__(128) k_softmax(float* __restrict__ att) {
    float* p = att + (size_t)blockIdx.x * C;
    float v0 = p[threadIdx.x], v1 = p[threadIdx.x + 128], v2 = p[threadIdx.x + 256];
    float mx = fmaxf(v0, fmaxf(v1, v2));
    __shared__ float sh[4], sh2[4];
    #pragma unroll
    for (int o = 16; o; o >>= 1) mx = fmaxf(mx, __shfl_xor_sync(0xffffffffu, mx, o));
    if ((threadIdx.x & 31) == 0) sh[threadIdx.x >> 5] = mx;
    __syncthreads();
    mx = fmaxf(fmaxf(sh[0], sh[1]), fmaxf(sh[2], sh[3]));
    v0 = __expf(v0 - mx); v1 = __expf(v1 - mx); v2 = __expf(v2 - mx);
    float s = v0 + v1 + v2;
    #pragma unroll
    for (int o = 16; o; o >>= 1) s += __shfl_xor_sync(0xffffffffu, s, o);
    if ((threadIdx.x & 31) == 0) sh2[threadIdx.x >> 5] = s;
    __syncthreads();
    s = sh2[0] + sh2[1] + sh2[2] + sh2[3];
    float inv = 1.f / s;
    p[threadIdx.x] = v0 * inv; p[threadIdx.x + 128] = v1 * inv; p[threadIdx.x + 256] = v2 * inv;
}

// ---------------- spatial multi-head attention -----------------------------
// K/V in smem transposed to [m][d] (pad 36) -> float4 broadcast loads.
// 8-key tiles with a single rescale per tile.
__global__ void __launch_bounds__(256) k_spattn() {
    extern __shared__ float sh[];
    float* ks = sh;                 // [L][SPAD]
    float* vs = sh + L * SPAD;      // [L][SPAD]
    int n = blockIdx.x / HEADS, h = blockIdx.x % HEADS;
    const float* base = g_qkv + (size_t)n * C3 * L + (size_t)h * (3 * HD) * L;
    int l = threadIdx.x;
    #pragma unroll
    for (int d = 0; d < HD; d++) {
        ks[l * SPAD + d] = base[(HD + d) * L + l];
        vs[l * SPAD + d] = base[(2 * HD + d) * L + l];
    }
    float4 q4[8];
    #pragma unroll
    for (int d = 0; d < HD; d++) ((float*)q4)[d] = base[d * L + l];
    __syncthreads();

    float mx = -1e30f, sum = 0.f;
    float4 acc4[8];
    #pragma unroll
    for (int i = 0; i < 8; i++) acc4[i] = make_float4(0.f, 0.f, 0.f, 0.f);

    for (int m0 = 0; m0 < L; m0 += 8) {
        float s[8];
        #pragma unroll
        for (int j = 0; j < 8; j++) {
            const float4* kp = (const float4*)(ks + (m0 + j) * SPAD);
            float tsum = 0.f;
            #pragma unroll
            for (int i = 0; i < 8; i++) {
                float4 kv = kp[i];
                tsum += q4[i].x * kv.x + q4[i].y * kv.y + q4[i].z * kv.z + q4[i].w * kv.w;
            }
            s[j] = tsum * 0.17677669529663689f;
        }
        float tm = s[0];
        #pragma unroll
        for (int j = 1; j < 8; j++) tm = fmaxf(tm, s[j]);
        float nm = fmaxf(mx, tm);
        float f = __expf(mx - nm);
        sum *= f;
        #pragma unroll
        for (int i = 0; i < 8; i++) {
            acc4[i].x *= f; acc4[i].y *= f; acc4[i].z *= f; acc4[i].w *= f;
        }
        #pragma unroll
        for (int j = 0; j < 8; j++) {
            float p = __expf(s[j] - nm);
            sum += p;
            const float4* vp = (const float4*)(vs + (m0 + j) * SPAD);
            #pragma unroll
            for (int i = 0; i < 8; i++) {
                float4 vv = vp[i];
                acc4[i].x += p * vv.x; acc4[i].y += p * vv.y;
                acc4[i].z += p * vv.z; acc4[i].w += p * vv.w;
            }
        }
        mx = nm;
    }
    float inv = 1.f / sum;
    float* outp = g_vals + (size_t)n * C * L + (size_t)h * HD * L + l;
    #pragma unroll
    for (int d = 0; d < HD; d++) outp[d * L] = ((float*)acc4)[d] * inv;
}

// ---------------- depthwise convtranspose (k=8,s=4,p=2) + residual ---------
// 4 output pixels per thread (one x-quad), float4 I/O.
__global__ void __launch_bounds__(256) k_up(
    const float* __restrict__ x, const float* __restrict__ w,
    const float* __restrict__ ub, float* __restrict__ out)
{
    int idx = blockIdx.x * 256 + threadIdx.x;   // over NB*C*64*16 quads
    int xb = idx & 15;
    int yq = (idx >> 4) & 63;
    int c  = (idx >> 10) % C;
    int n  = idx / (1024 * C);
    const float* xdp = g_xd + ((size_t)n * C + c) * L;
    const float* wp  = w + c * 64;
    int iy1 = (yq + 2) >> 2;
    float res[4] = {0.f, 0.f, 0.f, 0.f};
    #pragma unroll
    for (int a = 0; a < 2; a++) {
        int iy = iy1 - a, ky = yq + 2 - 4 * iy;
        if ((unsigned)iy < 16u && (unsigned)ky < 8u) {
            const float* xr = xdp + iy * HH;
            float xm1 = (xb > 0)  ? xr[xb - 1] : 0.f;
            float x0  = xr[xb];
            float xp1 = (xb < 15) ? xr[xb + 1] : 0.f;
            const float* wr = wp + ky * 8;
            // p=0: (ix=xb,kx=2),(ix=xb-1,kx=6)   p=1: (xb,3),(xb-1,7)
            // p=2: (xb+1,0),(xb,4)               p=3: (xb+1,1),(xb,5)
            res[0] += x0 * wr[2];
            if (xb > 0)  res[0] += xm1 * wr[6];
            res[1] += x0 * wr[3];
            if (xb > 0)  res[1] += xm1 * wr[7];
            res[2] += x0 * wr[4];
            if (xb < 15) res[2] += xp1 * wr[0];
            res[3] += x0 * wr[5];
            if (xb < 15) res[3] += xp1 * wr[1];
        }
    }
    float4 xv = ((const float4*)x)[idx];
    float ubc = ub[c];
    ((float4*)out)[idx] = make_float4(xv.x + res[0] + ubc, xv.y + res[1] + ubc,
                                      xv.z + res[2] + ubc, xv.w + res[3] + ubc);
}

// ---------------- host launcher -------------------------------------------
#define GEMM_SMEM (6 * STG * 4)   // 61440 bytes

extern "C" void kernel_launch(void* const* d_in, const int* in_sizes, int n_in,
                              void* d_out, int out_size)
{
    const float* x        = (const float*)d_in[0];
    const float* dw_w     = (const float*)d_in[1];
    const float* bn_gamma = (const float*)d_in[2];
    const float* bn_beta  = (const float*)d_in[3];
    const float* bn_mean  = (const float*)d_in[4];
    const float* bn_var   = (const float*)d_in[5];
    const float* lnch_g   = (const float*)d_in[6];
    const float* lnch_b   = (const float*)d_in[7];
    const float* pw_ch    = (const float*)d_in[8];
    const float* outch_w  = (const float*)d_in[9];
    const float* outch_b  = (const float*)d_in[10];
    const float* lnsp_g   = (const float*)d_in[11];
    const float* lnsp_b   = (const float*)d_in[12];
    const float* pw_sp    = (const float*)d_in[13];
    const float* outsp_w  = (const float*)d_in[14];
    const float* outsp_b  = (const float*)d_in[15];
    const float* up_w     = (const float*)d_in[16];
    const float* up_b     = (const float*)d_in[17];
    float* out = (float*)d_out;

    float *xd, *xd2, *gn, *qkv, *att, *vals;
    cudaGetSymbolAddress((void**)&xd,   g_xd);
    cudaGetSymbolAddress((void**)&xd2,  g_xd2);
    cudaGetSymbolAddress((void**)&gn,   g_gn);
    cudaGetSymbolAddress((void**)&qkv,  g_qkv);
    cudaGetSymbolAddress((void**)&att,  g_att);
    cudaGetSymbolAddress((void**)&vals, g_vals);

    static int inited = 0;
    if (!inited) {
        cudaFuncSetAttribute(k_gemm_tc<0, 0>, cudaFuncAttributeMaxDynamicSharedMemorySize, GEMM_SMEM);
        cudaFuncSetAttribute(k_gemm_tc<1, 0>, cudaFuncAttributeMaxDynamicSharedMemorySize, GEMM_SMEM);
        cudaFuncSetAttribute(k_gemm_tc<0, 1>, cudaFuncAttributeMaxDynamicSharedMemorySize, GEMM_SMEM);
        cudaFuncSetAttribute(k_spattn, cudaFuncAttributeMaxDynamicSharedMemorySize,
                             2 * L * SPAD * sizeof(float));
        inited = 1;
    }

    // 1) downsample conv + BN
    k_dwconv<<<NB * C, 256>>>(x, dw_w, bn_gamma, bn_beta, bn_mean, bn_var);

    // 2-3) GroupNorm #1
    k_gnstats<<<NB, 1024>>>(xd);
    k_gnapply<<<(NB * C * L / 4) / 256, 256>>>(xd, gn, lnch_g, lnch_b);

    // 4) qkv[n] = pw_ch @ gn[n]
    k_gemm_tc<0, 0><<<dim3(L / 128, C3 / 128, NB), 256, GEMM_SMEM>>>(
        pw_ch, gn, qkv, C, C, L, L,
        0, (long)C * L, (long)C3 * L, 1.f, nullptr, 0, nullptr);

    // 5) scores[n] = q[n] @ k[n]^T / 16
    k_gemm_tc<1, 0><<<dim3(C / 128, C / 128, NB), 256, GEMM_SMEM>>>(
        qkv, qkv + (size_t)C * L, att, L, L, L, C,
        (long)C3 * L, (long)C3 * L, (long)C * C,
        1.f / 16.f, nullptr, 0, nullptr);

    // 6) softmax rows
    k_softmax<<<NB * C, 128>>>(att);

    // 7) vals[n] = att[n] @ v[n]
    k_gemm_tc<0, 0><<<dim3(L / 128, C / 128, NB), 256, GEMM_SMEM>>>(
        att, qkv + (size_t)2 * C * L, vals, C, C, L, L,
        (long)C * C, (long)C3 * L, (long)C * L,
        1.f, nullptr, 0, nullptr);

    // 8) xd2[n] = outch_w @ vals[n] + xd[n] + outch_b
    k_gemm_tc<0, 1><<<dim3(L / 128, C / 128, NB), 256, GEMM_SMEM>>>(
        outch_w, vals, xd2, C, C, L, L,
        0, (long)C * L, (long)C * L,
        1.f, xd, (long)C * L, outch_b);

    // 9-10) GroupNorm #2
    k_gnstats<<<NB, 1024>>>(xd2);
    k_gnapply<<<(NB * C * L / 4) / 256, 256>>>(xd2, gn, lnsp_g, lnsp_b);

    // 11) qkv[n] = pw_sp @ gn[n]
    k_gemm_tc<0, 0><<<dim3(L / 128, C3 / 128, NB), 256, GEMM_SMEM>>>(
        pw_sp, gn, qkv, C, C, L, L,
        0, (long)C * L, (long)C3 * L, 1.f, nullptr, 0, nullptr);

    // 12) fused spatial attention
    k_spattn<<<NB * HEADS, 256, 2 * L * SPAD * sizeof(float)>>>();

    // 13) xd[n] = outsp_w @ vals[n] + xd2[n] + outsp_b
    k_gemm_tc<0, 1><<<dim3(L / 128, C / 128, NB), 256, GEMM_SMEM>>>(
        outsp_w, vals, xd, C, C, L, L,
        0, (long)C * L, (long)C * L,
        1.f, xd2, (long)C * L, outsp_b);

    // 14) upsample transposed conv + residual (4 px / thread)
    k_up<<<(NB * C * HIN * HIN / 4) / 256, 256>>>(x, up_w, up_b, out);
}

// round 8
// speedup vs baseline: 2.8724x; 1.1859x over previous
#include <cuda_runtime.h>
#include <math.h>
#include <stdint.h>

#define NB    16
#define C     384
#define C3    1152
#define HIN   64
#define HH    16
#define L     256
#define HEADS 12
#define HD    32
#define EPS   1e-5f
#define KPAD  36

// ---------------- scratch (device globals) ---------------------------------
__device__ float g_xd  [NB * C  * L];
__device__ float g_xd2 [NB * C  * L];
__device__ float g_gn  [NB * C  * L];
__device__ float g_qkv [NB * C3 * L];
__device__ float g_att [NB * C  * C];
__device__ float g_vals[NB * C  * L];
__device__ float g_stat[NB * 2];

// ---------------- depthwise 7x7 stride-4 conv + folded BatchNorm -----------
__global__ void __launch_bounds__(256) k_dwconv(
    const float* __restrict__ x, const float* __restrict__ w,
    const float* __restrict__ bg, const float* __restrict__ bb,
    const float* __restrict__ bm, const float* __restrict__ bv)
{
    __shared__ float sx[HIN * HIN];
    __shared__ float sw[49];
    int n = blockIdx.x / C, c = blockIdx.x % C;
    const float4* xp4 = (const float4*)(x + ((size_t)n * C + c) * (HIN * HIN));
    #pragma unroll
    for (int i = 0; i < 4; i++)
        ((float4*)sx)[threadIdx.x + i * 256] = xp4[threadIdx.x + i * 256];
    if (threadIdx.x < 49) sw[threadIdx.x] = w[c * 49 + threadIdx.x];
    __syncthreads();

    float scale = bg[c] * rsqrtf(bv[c] + EPS);
    float bias  = bb[c] - bm[c] * scale;

    int oy = threadIdx.x >> 4, ox = threadIdx.x & 15;
    int iy0 = oy * 4 - 3, ix0 = ox * 4 - 3;
    float acc = 0.f;
    #pragma unroll
    for (int ky = 0; ky < 7; ky++) {
        int iy = iy0 + ky;
        if ((unsigned)iy < (unsigned)HIN) {
            #pragma unroll
            for (int kx = 0; kx < 7; kx++) {
                int ix = ix0 + kx;
                if ((unsigned)ix < (unsigned)HIN)
                    acc += sx[iy * HIN + ix] * sw[ky * 7 + kx];
            }
        }
    }
    g_xd[((size_t)n * C + c) * L + threadIdx.x] = acc * scale + bias;
}

// ---------------- GroupNorm (1 group) --------------------------------------
__device__ __forceinline__ float warpsum(float v) {
    #pragma unroll
    for (int o = 16; o; o >>= 1) v += __shfl_down_sync(0xffffffffu, v, o);
    return v;
}

__global__ void __launch_bounds__(1024) k_gnstats(const float* __restrict__ p0) {
    const float4* p = (const float4*)(p0 + (size_t)blockIdx.x * C * L);
    float s = 0.f, s2 = 0.f;
    for (int i = threadIdx.x; i < C * L / 4; i += 1024) {
        float4 t = p[i];
        s  += t.x + t.y + t.z + t.w;
        s2 += t.x * t.x + t.y * t.y + t.z * t.z + t.w * t.w;
    }
    __shared__ float a[32], b[32];
    s = warpsum(s); s2 = warpsum(s2);
    int w = threadIdx.x >> 5, ln = threadIdx.x & 31;
    if (ln == 0) { a[w] = s; b[w] = s2; }
    __syncthreads();
    if (w == 0) {
        s = a[ln]; s2 = b[ln];
        s = warpsum(s); s2 = warpsum(s2);
        if (ln == 0) {
            float inv = 1.f / (C * L);
            float mean = s * inv;
            float var  = s2 * inv - mean * mean;
            g_stat[blockIdx.x * 2]     = mean;
            g_stat[blockIdx.x * 2 + 1] = rsqrtf(var + EPS);
        }
    }
}

__global__ void __launch_bounds__(256) k_gnapply(
    const float* __restrict__ in, float* __restrict__ out,
    const float* __restrict__ gamma, const float* __restrict__ beta)
{
    int i4 = blockIdx.x * 256 + threadIdx.x;
    int idx = i4 << 2;
    int n = idx / (C * L);
    int c = (idx / L) % C;
    float mean = g_stat[n * 2], istd = g_stat[n * 2 + 1];
    float g = gamma[c] * istd, bt = beta[c] - mean * g;
    float4 v = ((const float4*)in)[i4];
    ((float4*)out)[i4] = make_float4(v.x * g + bt, v.y * g + bt,
                                     v.z * g + bt, v.w * g + bt);
}

// ---------------- tf32 mma + cp.async helpers ------------------------------
__device__ __forceinline__ void mma_tf32(float c[4], const uint32_t a[4], const uint32_t b[2]) {
    asm volatile(
        "mma.sync.aligned.m16n8k8.row.col.f32.tf32.tf32.f32 "
        "{%0,%1,%2,%3}, {%4,%5,%6,%7}, {%8,%9}, {%0,%1,%2,%3};"
        : "+f"(c[0]), "+f"(c[1]), "+f"(c[2]), "+f"(c[3])
        : "r"(a[0]), "r"(a[1]), "r"(a[2]), "r"(a[3]), "r"(b[0]), "r"(b[1]));
}
__device__ __forceinline__ void cpa16(uint32_t s, const float* g) {
    asm volatile("cp.async.cg.shared.global [%0], [%1], 16;" :: "r"(s), "l"(g));
}

// ---------------- tf32 tensor-core GEMM, 3-stage pipeline ------------------
#define STG 2560
template<int TRANSB, int EPI>
__global__ void __launch_bounds__(256) k_gemm_tc(
    const float* __restrict__ A, const float* __restrict__ B, float* __restrict__ Cm,
    int K, int lda, int ldb, int ldc,
    long sA, long sB, long sC,
    float alpha, const float* __restrict__ R, long sR, const float* __restrict__ bias)
{
    extern __shared__ float smem[];
    int b = blockIdx.z;
    const float* Ab = A + (size_t)b * sA;
    const float* Bb = B + (size_t)b * sB;
    int t = threadIdx.x;
    int rowBase = blockIdx.y * 128, colBase = blockIdx.x * 128;

    int ar = t >> 2, ac = (t & 3) << 2;
    int bk = t >> 5, bc = (t & 31) << 2;

    uint32_t asB = (uint32_t)__cvta_generic_to_shared(smem);
    uint32_t buB = (uint32_t)__cvta_generic_to_shared(smem + 3 * STG);

    auto loadStage = [&](int k0, int st) {
        const float* ap = Ab + (size_t)(rowBase + ar) * lda + k0 + ac;
        uint32_t a0 = asB + (uint32_t)(st * STG + ar * 20 + ac) * 4;
        cpa16(a0,               ap);
        cpa16(a0 + 64 * 20 * 4, ap + (size_t)64 * lda);
        if (TRANSB) {
            const float* bp = Bb + (size_t)(colBase + ar) * ldb + k0 + ac;
            uint32_t b0 = buB + (uint32_t)(st * STG + ar * 20 + ac) * 4;
            cpa16(b0,               bp);
            cpa16(b0 + 64 * 20 * 4, bp + (size_t)64 * ldb);
        } else {
            const float* bp = Bb + (size_t)(k0 + bk) * ldb + colBase + bc;
            uint32_t b0 = buB + (uint32_t)(st * STG + bk * 136 + bc) * 4;
            cpa16(b0,                bp);
            cpa16(b0 + 8 * 136 * 4,  bp + (size_t)8 * ldb);
        }
    };

    int nIter = K >> 4;
    loadStage(0, 0);
    asm volatile("cp.async.commit_group;");
    loadStage(16, 1);
    asm volatile("cp.async.commit_group;");

    int lane = t & 31, w = t >> 5;
    int wm = (w >> 2) * 64, wn = (w & 3) * 32;
    int lk = lane & 3, lm = lane >> 2;
    float acc[4][4][4] = {};

    int cur = 0;
    for (int it = 0; it < nIter; ++it) {
        if (it + 2 < nIter) { asm volatile("cp.async.wait_group 1;"); }
        else               { asm volatile("cp.async.wait_group 0;"); }
        __syncthreads();
        if (it + 2 < nIter) {
            int st = cur - 1; if (st < 0) st += 3;
            loadStage((it + 2) << 4, st);
            asm volatile("cp.async.commit_group;");
        }
        const float* Asc = smem + cur * STG;
        const float* Bsc = smem + 3 * STG + cur * STG;
        #pragma unroll
        for (int kk = 0; kk < 16; kk += 8) {
            uint32_t af[4][4], bf[4][2];
            #pragma unroll
            for (int mi = 0; mi < 4; mi++) {
                int row = wm + mi * 16 + lm;
                af[mi][0] = __float_as_uint(Asc[row * 20 + kk + lk]);
                af[mi][1] = __float_as_uint(Asc[(row + 8) * 20 + kk + lk]);
                af[mi][2] = __float_as_uint(Asc[row * 20 + kk + 4 + lk]);
                af[mi][3] = __float_as_uint(Asc[(row + 8) * 20 + kk + 4 + lk]);
            }
            #pragma unroll
            for (int ni = 0; ni < 4; ni++) {
                int col = wn + ni * 8 + lm;
                if (TRANSB) {
                    bf[ni][0] = __float_as_uint(Bsc[col * 20 + kk + lk]);
                    bf[ni][1] = __float_as_uint(Bsc[col * 20 + kk + 4 + lk]);
                } else {
                    bf[ni][0] = __float_as_uint(Bsc[(kk + lk) * 136 + col]);
                    bf[ni][1] = __float_as_uint(Bsc[(kk + 4 + lk) * 136 + col]);
                }
            }
            #pragma unroll
            for (int mi = 0; mi < 4; mi++)
                #pragma unroll
                for (int ni = 0; ni < 4; ni++)
                    mma_tf32(acc[mi][ni], af[mi], bf[ni]);
        }
        cur++; if (cur == 3) cur = 0;
    }

    float* Cb = Cm + (size_t)b * sC;
    const float* Rb = (EPI == 1) ? (R + (size_t)b * sR) : nullptr;
    #pragma unroll
    for (int mi = 0; mi < 4; mi++) {
        #pragma unroll
        for (int ni = 0; ni < 4; ni++) {
            int r0 = rowBase + wm + mi * 16 + lm;
            int cc = colBase + wn + ni * 8 + 2 * lk;
            if (EPI == 1) {
                float bv0 = bias[r0], bv1 = bias[r0 + 8];
                float2 rv0 = *(const float2*)(Rb + (size_t)r0 * ldc + cc);
                float2 rv1 = *(const float2*)(Rb + (size_t)(r0 + 8) * ldc + cc);
                *(float2*)(Cb + (size_t)r0 * ldc + cc) =
                    make_float2(acc[mi][ni][0] + rv0.x + bv0, acc[mi][ni][1] + rv0.y + bv0);
                *(float2*)(Cb + (size_t)(r0 + 8) * ldc + cc) =
                    make_float2(acc[mi][ni][2] + rv1.x + bv1, acc[mi][ni][3] + rv1.y + bv1);
            } else {
                *(float2*)(Cb + (size_t)r0 * ldc + cc) =
                    make_float2(acc[mi][ni][0] * alpha, acc[mi][ni][1] * alpha);
                *(float2*)(Cb + (size_t)(r0 + 8) * ldc + cc) =
                    make_float2(acc[mi][ni][2] * alpha, acc[mi][ni][3] * alpha);
            }
        }
    }
}

// ---------------- channel-attention softmax (rows of 384) ------------------
__global__ void __launch_bounds__(128) k_softmax(float* __restrict__ att) {
    float* p = att + (size_t)blockIdx.x * C;
    float v0 = p[threadIdx.x], v1 = p[threadIdx.x + 128], v2 = p[threadIdx.x + 256];
    float mx = fmaxf(v0, fmaxf(v1, v2));
    __shared__ float sh[4], sh2[4];
    #pragma unroll
    for (int o = 16; o; o >>= 1) mx = fmaxf(mx, __shfl_xor_sync(0xffffffffu, mx, o));
    if ((threadIdx.x & 31) == 0) sh[threadIdx.x >> 5] = mx;
    __syncthreads();
    mx = fmaxf(fmaxf(sh[0], sh[1]), fmaxf(sh[2], sh[3]));
    v0 = __expf(v0 - mx); v1 = __expf(v1 - mx); v2 = __expf(v2 - mx);
    float s = v0 + v1 + v2;
    #pragma unroll
    for (int o = 16; o; o >>= 1) s += __shfl_xor_sync(0xffffffffu, s, o);
    if ((threadIdx.x & 31) == 0) sh2[threadIdx.x >> 5] = s;
    __syncthreads();
    s = sh2[0] + sh2[1] + sh2[2] + sh2[3];
    float inv = 1.f / s;
    p[threadIdx.x] = v0 * inv; p[threadIdx.x + 128] = v1 * inv; p[threadIdx.x + 256] = v2 * inv;
}

// ---------------- spatial attention: flash-style tf32 MMA ------------------
// One block per (n, head). 8 warps x 32 query rows. K^T/V^T staged in smem,
// Q fragments in registers (pre-scaled), S in 32-key chunks via mma, online
// softmax on C-fragments, P re-fragmented through per-warp smem for P@V.
__global__ void __launch_bounds__(256) k_spattn_mma() {
    extern __shared__ float sh[];
    float* KT  = sh;                       // [256][KPAD]
    float* VT  = sh + 256 * KPAD;          // [256][KPAD]
    float* Psm = sh + 2 * 256 * KPAD;      // 8 warps x [32][KPAD]
    int n = blockIdx.x / HEADS, h = blockIdx.x % HEADS;
    const float* base = g_qkv + (size_t)n * C3 * L + (size_t)h * (3 * HD) * L;
    int t = threadIdx.x, lane = t & 31, w = t >> 5;

    // stage K^T, V^T : gmem (d, l) -> smem [l][d]
    for (int i = t; i < HD * L; i += 256) {
        int d = i >> 8, l = i & 255;
        KT[l * KPAD + d] = base[(HD + d) * L + l];
        VT[l * KPAD + d] = base[(2 * HD + d) * L + l];
    }

    int lm = lane >> 2, lk = lane & 3;
    int qb = w * 32;
    const float scl = 0.17677669529663689f;   // 1/sqrt(32)
    uint32_t qf[2][4][4];
    #pragma unroll
    for (int mi = 0; mi < 2; mi++) {
        int r0 = qb + mi * 16 + lm;
        #pragma unroll
        for (int ks = 0; ks < 4; ks++) {
            int k0 = ks * 8;
            qf[mi][ks][0] = __float_as_uint(base[(k0 + lk) * L + r0]     * scl);
            qf[mi][ks][1] = __float_as_uint(base[(k0 + lk) * L + r0 + 8] * scl);
            qf[mi][ks][2] = __float_as_uint(base[(k0 + 4 + lk) * L + r0]     * scl);
            qf[mi][ks][3] = __float_as_uint(base[(k0 + 4 + lk) * L + r0 + 8] * scl);
        }
    }
    __syncthreads();

    float* Pw = Psm + w * 32 * KPAD;
    float m[4], lsum[4];
    #pragma unroll
    for (int i = 0; i < 4; i++) { m[i] = -1e30f; lsum[i] = 0.f; }
    float oacc[2][4][4] = {};

    for (int c0 = 0; c0 < L; c0 += 32) {
        // ---- S chunk = Q @ K^T  [32 rows x 32 keys] ----
        float sacc[2][4][4] = {};
        #pragma unroll
        for (int ks = 0; ks < 4; ks++) {
            int kk = ks * 8;
            uint32_t bf[4][2];
            #pragma unroll
            for (int ni = 0; ni < 4; ni++) {
                int col = c0 + ni * 8 + lm;
                bf[ni][0] = __float_as_uint(KT[col * KPAD + kk + lk]);
                bf[ni][1] = __float_as_uint(KT[col * KPAD + kk + 4 + lk]);
            }
            #pragma unroll
            for (int mi = 0; mi < 2; mi++)
                #pragma unroll
                for (int ni = 0; ni < 4; ni++)
                    mma_tf32(sacc[mi][ni], qf[mi][ks], bf[ni]);
        }
        // ---- online softmax over the 32 chunk columns ----
        #pragma unroll
        for (int mi = 0; mi < 2; mi++) {
            float cm0 = -1e30f, cm1 = -1e30f;
            #pragma unroll
            for (int ni = 0; ni < 4; ni++) {
                cm0 = fmaxf(cm0, fmaxf(sacc[mi][ni][0], sacc[mi][ni][1]));
                cm1 = fmaxf(cm1, fmaxf(sacc[mi][ni][2], sacc[mi][ni][3]));
            }
            cm0 = fmaxf(cm0, __shfl_xor_sync(0xffffffffu, cm0, 1));
            cm0 = fmaxf(cm0, __shfl_xor_sync(0xffffffffu, cm0, 2));
            cm1 = fmaxf(cm1, __shfl_xor_sync(0xffffffffu, cm1, 1));
            cm1 = fmaxf(cm1, __shfl_xor_sync(0xffffffffu, cm1, 2));
            float nm0 = fmaxf(m[2 * mi],     cm0);
            float nm1 = fmaxf(m[2 * mi + 1], cm1);
            float f0 = __expf(m[2 * mi] - nm0);
            float f1 = __expf(m[2 * mi + 1] - nm1);
            float ps0 = 0.f, ps1 = 0.f;
            int rA = (mi * 16 + lm) * KPAD, rB = (mi * 16 + lm + 8) * KPAD;
            #pragma unroll
            for (int ni = 0; ni < 4; ni++) {
                float p0 = __expf(sacc[mi][ni][0] - nm0);
                float p1 = __expf(sacc[mi][ni][1] - nm0);
                float p2 = __expf(sacc[mi][ni][2] - nm1);
                float p3 = __expf(sacc[mi][ni][3] - nm1);
                ps0 += p0 + p1; ps1 += p2 + p3;
                int col = ni * 8 + 2 * lk;
                Pw[rA + col] = p0; Pw[rA + col + 1] = p1;
                Pw[rB + col] = p2; Pw[rB + col + 1] = p3;
            }
            ps0 += __shfl_xor_sync(0xffffffffu, ps0, 1);
            ps0 += __shfl_xor_sync(0xffffffffu, ps0, 2);
            ps1 += __shfl_xor_sync(0xffffffffu, ps1, 1);
            ps1 += __shfl_xor_sync(0xffffffffu, ps1, 2);
            lsum[2 * mi]     = lsum[2 * mi]     * f0 + ps0;
            lsum[2 * mi + 1] = lsum[2 * mi + 1] * f1 + ps1;
            #pragma unroll
            for (int ni = 0; ni < 4; ni++) {
                oacc[mi][ni][0] *= f0; oacc[mi][ni][1] *= f0;
                oacc[mi][ni][2] *= f1; oacc[mi][ni][3] *= f1;
            }
            m[2 * mi] = nm0; m[2 * mi + 1] = nm1;
        }
        __syncwarp();
        // ---- O += P @ V chunk ----
        #pragma unroll
        for (int ks = 0; ks < 4; ks++) {
            int kk = ks * 8;
            uint32_t af[2][4], bf[4][2];
            #pragma unroll
            for (int mi = 0; mi < 2; mi++) {
                int row = mi * 16 + lm;
                af[mi][0] = __float_as_uint(Pw[row * KPAD + kk + lk]);
                af[mi][1] = __float_as_uint(Pw[(row + 8) * KPAD + kk + lk]);
                af[mi][2] = __float_as_uint(Pw[row * KPAD + kk + 4 + lk]);
                af[mi][3] = __float_as_uint(Pw[(row + 8) * KPAD + kk + 4 + lk]);
            }
            #pragma unroll
            for (int ni = 0; ni < 4; ni++) {
                int dcol = ni * 8 + lm;
                bf[ni][0] = __float_as_uint(VT[(c0 + kk + lk) * KPAD + dcol]);
                bf[ni][1] = __float_as_uint(VT[(c0 + kk + 4 + lk) * KPAD + dcol]);
            }
            #pragma unroll
            for (int mi = 0; mi < 2; mi++)
                #pragma unroll
                for (int ni = 0; ni < 4; ni++)
                    mma_tf32(oacc[mi][ni], af[mi], bf[ni]);
        }
        __syncwarp();
    }

    // ---- finalize and store: out(d, l) ----
    float inv[4];
    #pragma unroll
    for (int i = 0; i < 4; i++) inv[i] = 1.f / lsum[i];
    float* outp = g_vals + (size_t)n * C * L + (size_t)h * HD * L;
    #pragma unroll
    for (int mi = 0; mi < 2; mi++) {
        int r0 = qb + mi * 16 + lm;
        #pragma unroll
        for (int ni = 0; ni < 4; ni++) {
            int cc = ni * 8 + 2 * lk;
            outp[cc * L + r0]           = oacc[mi][ni][0] * inv[2 * mi];
            outp[(cc + 1) * L + r0]     = oacc[mi][ni][1] * inv[2 * mi];
            outp[cc * L + r0 + 8]       = oacc[mi][ni][2] * inv[2 * mi + 1];
            outp[(cc + 1) * L + r0 + 8] = oacc[mi][ni][3] * inv[2 * mi + 1];
        }
    }
}

// ---------------- depthwise convtranspose (k=8,s=4,p=2) + residual ---------
__global__ void __launch_bounds__(256) k_up(
    const float* __restrict__ x, const float* __restrict__ w,
    const float* __restrict__ ub, float* __restrict__ out)
{
    int idx = blockIdx.x * 256 + threadIdx.x;
    int xb = idx & 15;
    int yq = (idx >> 4) & 63;
    int c  = (idx >> 10) % C;
    int n  = idx / (1024 * C);
    const float* xdp = g_xd + ((size_t)n * C + c) * L;
    const float* wp  = w + c * 64;
    int iy1 = (yq + 2) >> 2;
    float res[4] = {0.f, 0.f, 0.f, 0.f};
    #pragma unroll
    for (int a = 0; a < 2; a++) {
        int iy = iy1 - a, ky = yq + 2 - 4 * iy;
        if ((unsigned)iy < 16u && (unsigned)ky < 8u) {
            const float* xr = xdp + iy * HH;
            float xm1 = (xb > 0)  ? xr[xb - 1] : 0.f;
            float x0  = xr[xb];
            float xp1 = (xb < 15) ? xr[xb + 1] : 0.f;
            const float* wr = wp + ky * 8;
            res[0] += x0 * wr[2];
            if (xb > 0)  res[0] += xm1 * wr[6];
            res[1] += x0 * wr[3];
            if (xb > 0)  res[1] += xm1 * wr[7];
            res[2] += x0 * wr[4];
            if (xb < 15) res[2] += xp1 * wr[0];
            res[3] += x0 * wr[5];
            if (xb < 15) res[3] += xp1 * wr[1];
        }
    }
    float4 xv = ((const float4*)x)[idx];
    float ubc = ub[c];
    ((float4*)out)[idx] = make_float4(xv.x + res[0] + ubc, xv.y + res[1] + ubc,
                                      xv.z + res[2] + ubc, xv.w + res[3] + ubc);
}

// ---------------- host launcher -------------------------------------------
#define GEMM_SMEM (6 * STG * 4)
#define SPATTN_SMEM ((2 * 256 * KPAD + 8 * 32 * KPAD) * 4)

extern "C" void kernel_launch(void* const* d_in, const int* in_sizes, int n_in,
                              void* d_out, int out_size)
{
    const float* x        = (const float*)d_in[0];
    const float* dw_w     = (const float*)d_in[1];
    const float* bn_gamma = (const float*)d_in[2];
    const float* bn_beta  = (const float*)d_in[3];
    const float* bn_mean  = (const float*)d_in[4];
    const float* bn_var   = (const float*)d_in[5];
    const float* lnch_g   = (const float*)d_in[6];
    const float* lnch_b   = (const float*)d_in[7];
    const float* pw_ch    = (const float*)d_in[8];
    const float* outch_w  = (const float*)d_in[9];
    const float* outch_b  = (const float*)d_in[10];
    const float* lnsp_g   = (const float*)d_in[11];
    const float* lnsp_b   = (const float*)d_in[12];
    const float* pw_sp    = (const float*)d_in[13];
    const float* outsp_w  = (const float*)d_in[14];
    const float* outsp_b  = (const float*)d_in[15];
    const float* up_w     = (const float*)d_in[16];
    const float* up_b     = (const float*)d_in[17];
    float* out = (float*)d_out;

    float *xd, *xd2, *gn, *qkv, *att, *vals;
    cudaGetSymbolAddress((void**)&xd,   g_xd);
    cudaGetSymbolAddress((void**)&xd2,  g_xd2);
    cudaGetSymbolAddress((void**)&gn,   g_gn);
    cudaGetSymbolAddress((void**)&qkv,  g_qkv);
    cudaGetSymbolAddress((void**)&att,  g_att);
    cudaGetSymbolAddress((void**)&vals, g_vals);

    // attribute calls are idempotent + capture-safe; run them unconditionally
    cudaFuncSetAttribute(k_gemm_tc<0, 0>, cudaFuncAttributeMaxDynamicSharedMemorySize, GEMM_SMEM);
    cudaFuncSetAttribute(k_gemm_tc<1, 0>, cudaFuncAttributeMaxDynamicSharedMemorySize, GEMM_SMEM);
    cudaFuncSetAttribute(k_gemm_tc<0, 1>, cudaFuncAttributeMaxDynamicSharedMemorySize, GEMM_SMEM);
    cudaFuncSetAttribute(k_spattn_mma, cudaFuncAttributeMaxDynamicSharedMemorySize, SPATTN_SMEM);

    // 1) downsample conv + BN
    k_dwconv<<<NB * C, 256>>>(x, dw_w, bn_gamma, bn_beta, bn_mean, bn_var);

    // 2-3) GroupNorm #1
    k_gnstats<<<NB, 1024>>>(xd);
    k_gnapply<<<(NB * C * L / 4) / 256, 256>>>(xd, gn, lnch_g, lnch_b);

    // 4) qkv[n] = pw_ch @ gn[n]
    k_gemm_tc<0, 0><<<dim3(L / 128, C3 / 128, NB), 256, GEMM_SMEM>>>(
        pw_ch, gn, qkv, C, C, L, L,
        0, (long)C * L, (long)C3 * L, 1.f, nullptr, 0, nullptr);

    // 5) scores[n] = q[n] @ k[n]^T / 16
    k_gemm_tc<1, 0><<<dim3(C / 128, C / 128, NB), 256, GEMM_SMEM>>>(
        qkv, qkv + (size_t)C * L, att, L, L, L, C,
        (long)C3 * L, (long)C3 * L, (long)C * C,
        1.f / 16.f, nullptr, 0, nullptr);

    // 6) softmax rows
    k_softmax<<<NB * C, 128>>>(att);

    // 7) vals[n] = att[n] @ v[n]
    k_gemm_tc<0, 0><<<dim3(L / 128, C / 128, NB), 256, GEMM_SMEM>>>(
        att, qkv + (size_t)2 * C * L, vals, C, C, L, L,
        (long)C * C, (long)C3 * L, (long)C * L,
        1.f, nullptr, 0, nullptr);

    // 8) xd2[n] = outch_w @ vals[n] + xd[n] + outch_b
    k_gemm_tc<0, 1><<<dim3(L / 128, C / 128, NB), 256, GEMM_SMEM>>>(
        outch_w, vals, xd2, C, C, L, L,
        0, (long)C * L, (long)C * L,
        1.f, xd, (long)C * L, outch_b);

    // 9-10) GroupNorm #2
    k_gnstats<<<NB, 1024>>>(xd2);
    k_gnapply<<<(NB * C * L / 4) / 256, 256>>>(xd2, gn, lnsp_g, lnsp_b);

    // 11) qkv[n] = pw_sp @ gn[n]
    k_gemm_tc<0, 0><<<dim3(L / 128, C3 / 128, NB), 256, GEMM_SMEM>>>(
        pw_sp, gn, qkv, C, C, L, L,
        0, (long)C * L, (long)C3 * L, 1.f, nullptr, 0, nullptr);

    // 12) fused spatial attention (tensor-core flash)
    k_spattn_mma<<<NB * HEADS, 256, SPATTN_SMEM>>>();

    // 13) xd[n] = outsp_w @ vals[n] + xd2[n] + outsp_b
    k_gemm_tc<0, 1><<<dim3(L / 128, C / 128, NB), 256, GEMM_SMEM>>>(
        outsp_w, vals, xd, C, C, L, L,
        0, (long)C * L, (long)C * L,
        1.f, xd2, (long)C * L, outsp_b);

    // 14) upsample transposed conv + residual
    k_up<<<(NB * C * HIN * HIN / 4) / 256, 256>>>(x, up_w, up_b, out);
}